// round 4
// baseline (speedup 1.0000x reference)
#include <cuda_runtime.h>
#include <cstdint>

// Problem constants (fixed by setup_inputs)
#define N_NODES 8192
#define IN_DIM  256
#define OUT_DIM 64
#define SLOPE   0.2f

#define GEMM_BLOCKS 128
#define LCAP 256          // per-row neighbor list capacity (mean deg 82, sd 9)

// Scratch (allocation-free rule: __device__ globals)
__device__ float          g_proj[N_NODES * OUT_DIM];        // 2 MB
__device__ float          g_si[N_NODES];
__device__ float          g_sj[N_NODES];
__device__ unsigned short g_lists[(size_t)N_NODES * LCAP];  // 4 MB
__device__ int            g_cnt[N_NODES];

// ---------------------------------------------------------------------------
// Kernel 1 (fused): blocks [0,128) compute proj = X@W + s_i/s_j epilogue;
// blocks [128, 128+8192) scan one adjacency row each into a uint16 CSR list.
// The scan is DRAM-bound; the GEMM hides under it.
// ---------------------------------------------------------------------------
#define GM_BM 64
#define GM_BK 32
#define AS_LD 68   // 64 + 4 padding

__global__ __launch_bounds__(256) void fused_gemm_scan_kernel(
    const float* __restrict__ X, const float* __restrict__ W,
    const float* __restrict__ a, const unsigned* __restrict__ adj)
{
    __shared__ float As[2][GM_BK * AS_LD];
    __shared__ float Bs[2][GM_BK][OUT_DIM];
    __shared__ float a_s[2 * OUT_DIM];
    __shared__ int   s_wc[8];

    const int tid  = threadIdx.x;
    const int lane = tid & 31;
    const int warp = tid >> 5;

    if (blockIdx.x >= GEMM_BLOCKS) {
        // =================== adjacency row scan path ===================
        const int row = blockIdx.x - GEMM_BLOCKS;
        const uint4* arow4 = (const uint4*)(adj + (size_t)row * N_NODES); // 2048 uint4

        // warp w owns uint4 range [w*256, (w+1)*256): 8 iters x 32 lanes.
        uint4 v[8];
        #pragma unroll
        for (int i = 0; i < 8; i++)
            v[i] = arow4[warp * 256 + i * 32 + lane];     // 8 LDG.128 in flight

        unsigned mk[8][4];
        int wcnt = 0;
        #pragma unroll
        for (int i = 0; i < 8; i++) {
            mk[i][0] = __ballot_sync(0xffffffffu, v[i].x != 0u);
            mk[i][1] = __ballot_sync(0xffffffffu, v[i].y != 0u);
            mk[i][2] = __ballot_sync(0xffffffffu, v[i].z != 0u);
            mk[i][3] = __ballot_sync(0xffffffffu, v[i].w != 0u);
            wcnt += __popc(mk[i][0]) + __popc(mk[i][1])
                  + __popc(mk[i][2]) + __popc(mk[i][3]);
        }

        if (lane == 0) s_wc[warp] = wcnt;
        __syncthreads();
        int base = 0, total = 0;
        #pragma unroll
        for (int w = 0; w < 8; w++) {
            int c = s_wc[w];
            if (w < warp) base += c;
            total += c;
        }

        if (total <= LCAP) {
            int off = base;
            const unsigned lt = (1u << lane) - 1u;
            #pragma unroll
            for (int i = 0; i < 8; i++) {
                #pragma unroll
                for (int c = 0; c < 4; c++) {
                    unsigned m = mk[i][c];
                    if (m & (1u << lane)) {
                        int pos = off + __popc(m & lt);
                        // node index covered by uint4 (warp,i,lane) component c
                        g_lists[(size_t)row * LCAP + pos] =
                            (unsigned short)(warp * 1024 + i * 128 + 4 * lane + c);
                    }
                    off += __popc(m);
                }
            }
        }
        if (tid == 0) g_cnt[row] = total;
        return;
    }

    // ======================= GEMM + s epilogue path =======================
    const int block_row = blockIdx.x * GM_BM;
    const int trow = tid >> 4;
    const int tcol = tid & 15;

    if (tid < 128) a_s[tid] = a[tid];

    const int a_r0 = tid >> 3;
    const int a_c4 = tid & 7;
    const int a_r1 = (tid + 256) >> 3;
    const int b_r0 = tid >> 4;
    const int b_c4 = tid & 15;
    const int b_r1 = (tid + 256) >> 4;

    float4 rA0, rA1, rB0, rB1;

    auto load_tiles = [&](int k0) {
        rA0 = *(const float4*)(X + (size_t)(block_row + a_r0) * IN_DIM + k0 + a_c4 * 4);
        rA1 = *(const float4*)(X + (size_t)(block_row + a_r1) * IN_DIM + k0 + a_c4 * 4);
        rB0 = *(const float4*)(W + (size_t)(k0 + b_r0) * OUT_DIM + b_c4 * 4);
        rB1 = *(const float4*)(W + (size_t)(k0 + b_r1) * OUT_DIM + b_c4 * 4);
    };
    auto store_tiles = [&](int buf) {
        As[buf][(a_c4 * 4 + 0) * AS_LD + a_r0] = rA0.x;
        As[buf][(a_c4 * 4 + 1) * AS_LD + a_r0] = rA0.y;
        As[buf][(a_c4 * 4 + 2) * AS_LD + a_r0] = rA0.z;
        As[buf][(a_c4 * 4 + 3) * AS_LD + a_r0] = rA0.w;
        As[buf][(a_c4 * 4 + 0) * AS_LD + a_r1] = rA1.x;
        As[buf][(a_c4 * 4 + 1) * AS_LD + a_r1] = rA1.y;
        As[buf][(a_c4 * 4 + 2) * AS_LD + a_r1] = rA1.z;
        As[buf][(a_c4 * 4 + 3) * AS_LD + a_r1] = rA1.w;
        *(float4*)&Bs[buf][b_r0][b_c4 * 4] = rB0;
        *(float4*)&Bs[buf][b_r1][b_c4 * 4] = rB1;
    };

    float acc[4][4];
    #pragma unroll
    for (int i = 0; i < 4; i++)
        #pragma unroll
        for (int j = 0; j < 4; j++) acc[i][j] = 0.0f;

    load_tiles(0);
    store_tiles(0);
    __syncthreads();

    const int NT = IN_DIM / GM_BK;
    for (int t = 0; t < NT; t++) {
        int buf = t & 1;
        if (t + 1 < NT) load_tiles((t + 1) * GM_BK);

        #pragma unroll
        for (int k = 0; k < GM_BK; k++) {
            float4 av = *(const float4*)&As[buf][k * AS_LD + trow * 4];
            float4 bv = *(const float4*)&Bs[buf][k][tcol * 4];
            float aa[4] = {av.x, av.y, av.z, av.w};
            float bb[4] = {bv.x, bv.y, bv.z, bv.w};
            #pragma unroll
            for (int i = 0; i < 4; i++)
                #pragma unroll
                for (int j = 0; j < 4; j++)
                    acc[i][j] = fmaf(aa[i], bb[j], acc[i][j]);
        }
        if (t + 1 < NT) store_tiles(buf ^ 1);
        __syncthreads();
    }

    #pragma unroll
    for (int i = 0; i < 4; i++) {
        int row = block_row + trow * 4 + i;
        float4 vv = make_float4(acc[i][0], acc[i][1], acc[i][2], acc[i][3]);
        *(float4*)(g_proj + (size_t)row * OUT_DIM + tcol * 4) = vv;

        float q0 = acc[i][0] * a_s[tcol * 4 + 0] + acc[i][1] * a_s[tcol * 4 + 1]
                 + acc[i][2] * a_s[tcol * 4 + 2] + acc[i][3] * a_s[tcol * 4 + 3];
        float q1 = acc[i][0] * a_s[64 + tcol * 4 + 0] + acc[i][1] * a_s[64 + tcol * 4 + 1]
                 + acc[i][2] * a_s[64 + tcol * 4 + 2] + acc[i][3] * a_s[64 + tcol * 4 + 3];
        #pragma unroll
        for (int o = 8; o > 0; o >>= 1) {
            q0 += __shfl_down_sync(0xffffffffu, q0, o, 16);
            q1 += __shfl_down_sync(0xffffffffu, q1, o, 16);
        }
        if (tcol == 0) { g_si[row] = q0; g_sj[row] = q1; }
    }
}

// ---------------------------------------------------------------------------
// Kernel 2: softmax + gather from precomputed neighbor lists (no adjacency
// traffic on the fast path).
// ---------------------------------------------------------------------------
__device__ __forceinline__ float leaky(float x) {
    return x > 0.0f ? x : SLOPE * x;
}

__device__ __forceinline__ float block_reduce(float v, float* s8, bool do_max)
{
    int lane = threadIdx.x & 31;
    int warp = threadIdx.x >> 5;
    #pragma unroll
    for (int o = 16; o > 0; o >>= 1) {
        float t = __shfl_xor_sync(0xffffffffu, v, o);
        v = do_max ? fmaxf(v, t) : (v + t);
    }
    __syncthreads();
    if (lane == 0) s8[warp] = v;
    __syncthreads();
    if (threadIdx.x == 0) {
        float r = s8[0];
        #pragma unroll
        for (int w = 1; w < 8; w++)
            r = do_max ? fmaxf(r, s8[w]) : (r + s8[w]);
        s8[0] = r;
    }
    __syncthreads();
    return s8[0];
}

__global__ __launch_bounds__(256) void attn_kernel(
    const unsigned* __restrict__ adj, float* __restrict__ out)
{
    __shared__ int   s_id[LCAP];
    __shared__ float s_w[LCAP];
    __shared__ float s_acc[4][OUT_DIM];
    __shared__ float s_red[8];

    const int row = blockIdx.x;
    const int tid = threadIdx.x;
    const int cnt = g_cnt[row];

    const float si_r = g_si[row];
    const int   g    = tid >> 6;      // group 0..3
    const int   d    = tid & 63;      // output dim

    if (cnt > 0 && cnt <= LCAP) {
        // ---------------- fast path ----------------
        if (tid < cnt) s_id[tid] = g_lists[(size_t)row * LCAP + tid];
        __syncthreads();

        float lm = -INFINITY;
        float e0 = 0.0f;
        if (tid < cnt) {
            e0 = leaky(si_r + g_sj[s_id[tid]]);
            lm = e0;
        }
        float m = block_reduce(lm, s_red, true);

        float ls = 0.0f;
        if (tid < cnt) {
            float w = __expf(e0 - m);
            s_w[tid] = w;
            ls = w;
        }
        float denom = block_reduce(ls, s_red, false);

        float acc = 0.0f;
        #pragma unroll 4
        for (int k = g; k < cnt; k += 4)
            acc += s_w[k] * g_proj[(size_t)s_id[k] * OUT_DIM + d];
        s_acc[g][d] = acc;
        __syncthreads();
        if (g == 0) {
            float tot = s_acc[0][d] + s_acc[1][d] + s_acc[2][d] + s_acc[3][d];
            out[(size_t)row * OUT_DIM + d] = tot / denom;
        }
        return;
    }

    if (cnt == 0) {
        // softmax over all-NEG_BIG row is uniform: out = mean(proj)
        float acc = 0.0f;
        for (int j = g; j < N_NODES; j += 4)
            acc += g_proj[(size_t)j * OUT_DIM + d];
        s_acc[g][d] = acc;
        __syncthreads();
        if (g == 0) {
            float tot = s_acc[0][d] + s_acc[1][d] + s_acc[2][d] + s_acc[3][d];
            out[(size_t)row * OUT_DIM + d] = tot * (1.0f / (float)N_NODES);
        }
        return;
    }

    // ---------------- overflow fallback (cnt > LCAP, ~never) ----------------
    const unsigned* arow = adj + (size_t)row * N_NODES;
    float lm = -INFINITY;
    for (int j = tid; j < N_NODES; j += 256)
        if (arow[j]) lm = fmaxf(lm, leaky(si_r + g_sj[j]));
    float m = block_reduce(lm, s_red, true);

    float ls = 0.0f;
    for (int j = tid; j < N_NODES; j += 256)
        if (arow[j]) ls += __expf(leaky(si_r + g_sj[j]) - m);
    float denom = block_reduce(ls, s_red, false);

    float acc = 0.0f;
    for (int j = g; j < N_NODES; j += 4)
        if (arow[j]) {
            float w = __expf(leaky(si_r + g_sj[j]) - m);
            acc += w * g_proj[(size_t)j * OUT_DIM + d];
        }
    s_acc[g][d] = acc;
    __syncthreads();
    if (g == 0) {
        float tot = s_acc[0][d] + s_acc[1][d] + s_acc[2][d] + s_acc[3][d];
        out[(size_t)row * OUT_DIM + d] = tot / denom;
    }
}

// ---------------------------------------------------------------------------
// Launch
// ---------------------------------------------------------------------------
extern "C" void kernel_launch(void* const* d_in, const int* in_sizes, int n_in,
                              void* d_out, int out_size)
{
    const float*    X   = (const float*)d_in[0];
    const unsigned* adj = (const unsigned*)d_in[1];   // bool widened to 32-bit
    const float*    W   = (const float*)d_in[2];
    const float*    a   = (const float*)d_in[3];
    float*          out = (float*)d_out;

    fused_gemm_scan_kernel<<<GEMM_BLOCKS + N_NODES, 256>>>(X, W, a, adj);
    attn_kernel<<<N_NODES, 256>>>(adj, out);
}